// round 6
// baseline (speedup 1.0000x reference)
#include <cuda_runtime.h>
#include <math.h>
#include <stdint.h>

// Problem constants
#define RB 256      // batch
#define RT 512      // time steps
#define RH 1024     // hidden
#define RC 10       // classes

// Tiling
#define GB 4                 // batch groups
#define GJ 32                // j-tile CTAs per group
#define BT (RB / GB)         // 64  batch per CTA
#define JT (RH / GJ)         // 32  hidden-out per CTA
#define KC 128               // k chunk staged per cp.async round
#define NC (RH / KC)         // 8 chunks
#define NTHREADS 256

#define SMEM_W_FLOATS (RH * JT)        // 32768 floats = 128 KB (whh tile, [k][j])
#define SMEM_H_FLOATS (2 * KC * BT)    // 16384 floats = 64 KB  (h staging, [buf][k][b])
#define SMEM_BYTES ((SMEM_W_FLOATS + SMEM_H_FLOATS) * 4)   // 196608

// Persistent state (allowed: __device__ globals, no allocation)
__device__ float g_h[2][RH * RB];        // ping-pong hidden state, k-major: [k][b]
__device__ unsigned int g_bar[GB];       // per-group monotonic barrier counters

// ---------------- f32x2 helpers ----------------
__device__ __forceinline__ unsigned long long fma2(unsigned long long a,
                                                   unsigned long long b,
                                                   unsigned long long c) {
    unsigned long long d;
    asm("fma.rn.f32x2 %0, %1, %2, %3;" : "=l"(d) : "l"(a), "l"(b), "l"(c));
    return d;
}
__device__ __forceinline__ unsigned long long dup2(float v) {
    unsigned long long d;
    unsigned int r = __float_as_uint(v);
    asm("mov.b64 %0, {%1, %1};" : "=l"(d) : "r"(r));
    return d;
}
__device__ __forceinline__ float2 unpk(unsigned long long v) {
    unsigned int lo, hi;
    asm("mov.b64 {%0, %1}, %2;" : "=r"(lo), "=r"(hi) : "l"(v));
    float2 r;
    r.x = __uint_as_float(lo);
    r.y = __uint_as_float(hi);
    return r;
}

// Accurate tanh independent of fast-math tanhf lowering.
__device__ __forceinline__ float tanh_acc(float v) {
    float ax = fabsf(v);
    if (ax < 0.25f) {
        float s = v * v;
        float p = fmaf(s, 0.021869488f, -0.05396825397f);
        p = fmaf(s, p, 0.13333333333f);
        p = fmaf(s, p, -0.33333333333f);
        return fmaf(v * s, p, v);
    } else {
        float e = expf(-2.0f * ax);
        float r = (1.0f - e) / (1.0f + e);
        return copysignf(r, v);
    }
}

// cp.async one KC x BT chunk of h (k-major rows of 64 contiguous floats)
__device__ __forceinline__ void issue_chunk(unsigned int sm_h_base,
                                            const float* __restrict__ hin,
                                            int chunk, int buf, int b0) {
    const int tid = threadIdx.x;
    unsigned int dst0 = sm_h_base + (unsigned int)buf * (KC * BT * 4);
    const float* src0 = hin + chunk * KC * RB + b0;
#pragma unroll
    for (int i = 0; i < (KC * BT) / (4 * NTHREADS); ++i) {  // 8 segs/thread
        int seg = tid + i * NTHREADS;                       // 16B segment id
        int row = seg >> 4;                                 // 16 segs per 64-float row
        int col = seg & 15;
        unsigned int dst = dst0 + (unsigned int)seg * 16;
        const char* src = (const char*)(src0 + row * RB) + col * 16;
        asm volatile("cp.async.cg.shared.global [%0], [%1], 16;"
                     :: "r"(dst), "l"(src) : "memory");
    }
}

__global__ void __launch_bounds__(NTHREADS, 1)
rnn_init_kernel() {
    int idx = blockIdx.x * blockDim.x + threadIdx.x;
    if (idx < RH * RB) g_h[0][idx] = 0.0f;
    if (idx < GB) g_bar[idx] = 0u;
}

__global__ void __launch_bounds__(NTHREADS, 1)
rnn_persistent_kernel(const float* __restrict__ x,
                      const float* __restrict__ whx,
                      const float* __restrict__ whh,
                      const float* __restrict__ bias_h) {
    extern __shared__ float smem[];
    float* s_w = smem;                   // [RH][JT] : s_w[k*JT + jlocal] = whh[j][k]
    float* s_h = smem + SMEM_W_FLOATS;   // [2][KC][BT]

    const int tid = threadIdx.x;
    const int bid = blockIdx.x;
    const int bg = bid >> 5;             // 0..3
    const int jg = bid & 31;             // 0..31
    const int j0 = jg * JT;              // global j base
    const int b0 = bg * BT;              // global b base

    const int lane = tid & 31;
    const int warp = tid >> 5;
    const int j4 = lane & 7;             // 8 j-quads
    const int bp = (warp << 2) | (lane >> 3);   // 0..31 batch pairs
    const int bl = bp * 2;               // local b (even)
    const int jl = j4 * 4;               // local j base (quad)

    // Load whh tile once, transposed into SMEM: resident for all 512 steps.
    for (int idx = tid; idx < JT * (RH / 4); idx += NTHREADS) {
        int jloc = idx / (RH / 4);
        int k4 = (idx - jloc * (RH / 4)) * 4;
        float4 v = *reinterpret_cast<const float4*>(&whh[(j0 + jloc) * RH + k4]);
        s_w[(k4 + 0) * JT + jloc] = v.x;
        s_w[(k4 + 1) * JT + jloc] = v.y;
        s_w[(k4 + 2) * JT + jloc] = v.z;
        s_w[(k4 + 3) * JT + jloc] = v.w;
    }

    float whx_r[4], bias_r[4];
#pragma unroll
    for (int jj = 0; jj < 4; ++jj) {
        whx_r[jj]  = whx[j0 + jl + jj];
        bias_r[jj] = bias_h[j0 + jl + jj];
    }
    const int bg0 = b0 + bl;             // global b of this thread's batch pair

    __syncthreads();

    unsigned int sm_h_base = (unsigned int)__cvta_generic_to_shared(s_h);
    volatile unsigned int* barp = &g_bar[bg];

    for (int t = 0; t < RT; ++t) {
        const float* __restrict__ hin = &g_h[t & 1][0];
        float* __restrict__ hout = &g_h[(t + 1) & 1][0];

        issue_chunk(sm_h_base, hin, 0, 0, b0);
        asm volatile("cp.async.commit_group;" ::: "memory");
        issue_chunk(sm_h_base, hin, 1, 1, b0);
        asm volatile("cp.async.commit_group;" ::: "memory");

        unsigned long long a00 = 0ull, a01 = 0ull, a10 = 0ull, a11 = 0ull;

        for (int c = 0; c < NC; ++c) {
            if (c < NC - 1) asm volatile("cp.async.wait_group 1;" ::: "memory");
            else            asm volatile("cp.async.wait_group 0;" ::: "memory");
            __syncthreads();

            const float* hb = s_h + (c & 1) * (KC * BT) + bl;
            const float* wb = s_w + (c * KC) * JT + jl;
#pragma unroll 8
            for (int kk = 0; kk < KC; ++kk) {
                float2 hv = *reinterpret_cast<const float2*>(hb + kk * BT);
                ulonglong2 wv = *reinterpret_cast<const ulonglong2*>(wb + kk * JT);
                unsigned long long h0d = dup2(hv.x);
                unsigned long long h1d = dup2(hv.y);
                a00 = fma2(wv.x, h0d, a00);   // b0 x {j0,j1}
                a01 = fma2(wv.y, h0d, a01);   // b0 x {j2,j3}
                a10 = fma2(wv.x, h1d, a10);   // b1 x {j0,j1}
                a11 = fma2(wv.y, h1d, a11);   // b1 x {j2,j3}
            }
            __syncthreads();
            if (c + 2 < NC) {
                issue_chunk(sm_h_base, hin, c + 2, c & 1, b0);
                asm volatile("cp.async.commit_group;" ::: "memory");
            }
        }

        // Epilogue: add input + bias, tanh, write h_next (k-major, pairs over b)
        float2 v00 = unpk(a00), v01 = unpk(a01), v10 = unpk(a10), v11 = unpk(a11);
        float xb0 = x[bg0 * RT + t];
        float xb1 = x[(bg0 + 1) * RT + t];

        float h0[4], h1[4];
        h0[0] = tanh_acc(v00.x + fmaf(xb0, whx_r[0], bias_r[0]));
        h0[1] = tanh_acc(v00.y + fmaf(xb0, whx_r[1], bias_r[1]));
        h0[2] = tanh_acc(v01.x + fmaf(xb0, whx_r[2], bias_r[2]));
        h0[3] = tanh_acc(v01.y + fmaf(xb0, whx_r[3], bias_r[3]));
        h1[0] = tanh_acc(v10.x + fmaf(xb1, whx_r[0], bias_r[0]));
        h1[1] = tanh_acc(v10.y + fmaf(xb1, whx_r[1], bias_r[1]));
        h1[2] = tanh_acc(v11.x + fmaf(xb1, whx_r[2], bias_r[2]));
        h1[3] = tanh_acc(v11.y + fmaf(xb1, whx_r[3], bias_r[3]));

#pragma unroll
        for (int jj = 0; jj < 4; ++jj) {
            float2 o;
            o.x = h0[jj];
            o.y = h1[jj];
            *reinterpret_cast<float2*>(&hout[(j0 + jl + jj) * RB + bg0]) = o;
        }

        // Per-group barrier (32 CTAs), monotonic counter (reset by init kernel)
        __threadfence();
        __syncthreads();
        if (tid == 0) {
            atomicAdd(&g_bar[bg], 1u);
            unsigned int target = (unsigned int)(t + 1) * GJ;
            while (*barp < target) { }
            __threadfence();
        }
        __syncthreads();
    }
}

// p[b][c] = h_final[b] . wph[c] + bias_p[c];  h_final lives in g_h[0] (RT even)
__global__ void __launch_bounds__(RB, 1)
rnn_proj_kernel(const float* __restrict__ wph,
                const float* __restrict__ bias_p,
                float* __restrict__ out) {
    const int c = blockIdx.x;     // 0..9
    const int b = threadIdx.x;    // 0..255
    const float* __restrict__ hf = &g_h[0][0];
    const float* __restrict__ w = wph + c * RH;
    float a0 = 0.0f, a1 = 0.0f, a2 = 0.0f, a3 = 0.0f;
#pragma unroll 8
    for (int k = 0; k < RH; k += 4) {
        a0 = fmaf(hf[(k + 0) * RB + b], w[k + 0], a0);
        a1 = fmaf(hf[(k + 1) * RB + b], w[k + 1], a1);
        a2 = fmaf(hf[(k + 2) * RB + b], w[k + 2], a2);
        a3 = fmaf(hf[(k + 3) * RB + b], w[k + 3], a3);
    }
    out[b * RC + c] = (a0 + a1) + (a2 + a3) + bias_p[c];
}

extern "C" void kernel_launch(void* const* d_in, const int* in_sizes, int n_in,
                              void* d_out, int out_size) {
    (void)in_sizes; (void)n_in; (void)out_size;
    const float* x      = (const float*)d_in[0];   // [B, T]
    const float* whx    = (const float*)d_in[1];   // [H, 1]
    const float* whh    = (const float*)d_in[2];   // [H, H]
    const float* bias_h = (const float*)d_in[3];   // [H]
    const float* wph    = (const float*)d_in[4];   // [C, H]
    const float* bias_p = (const float*)d_in[5];   // [C]
    float* out = (float*)d_out;                    // [B, C]

    cudaFuncSetAttribute(rnn_persistent_kernel,
                         cudaFuncAttributeMaxDynamicSharedMemorySize, SMEM_BYTES);

    rnn_init_kernel<<<(RH * RB + NTHREADS - 1) / NTHREADS, NTHREADS>>>();
    rnn_persistent_kernel<<<GB * GJ, NTHREADS, SMEM_BYTES>>>(x, whx, whh, bias_h);
    rnn_proj_kernel<<<RC, RB>>>(wph, bias_p, out);
}

// round 8
// speedup vs baseline: 2.3342x; 2.3342x over previous
#include <cuda_runtime.h>
#include <cuda_bf16.h>
#include <math.h>
#include <stdint.h>

// Problem constants
#define RB 256      // batch
#define RT 512      // time steps
#define RH 1024     // hidden
#define RC 10       // classes

// Tiling: 4 batch groups (M=64) x 32 j-tiles (N=32) = 128 CTAs (1 per SM)
#define NM 4
#define NN 32
#define MT 64
#define NT 32
#define KC 128             // k per staged chunk
#define NCH 8              // chunks per step
#define NTH 256            // 8 warps

// SMEM byte layout (dynamic)
// W rows padded to 2064B (1032 bf16) for conflict-free ldmatrix (8-row stride)
#define W_PITCH 2064
#define SW_HI 0
#define SW_LO 66048
#define SA_OFF 132096
// A chunk: 64 rows x 272B (128 bf16 data + 16B pad) = 17408 per split
#define A_PITCH 272
#define A_SPLIT 17408
#define A_BUF 34816                      // hi + lo
#define SMEM_BYTES (SA_OFF + 2 * A_BUF)  // 201728

// Persistent state (device globals; no allocation)
__device__ __nv_bfloat16 g_hh[2][RB * RH];   // h hi, [b][k]
__device__ __nv_bfloat16 g_hl[2][RB * RH];   // h lo
__device__ unsigned int g_bar[NM];

// ----------------- helpers -----------------
__device__ __forceinline__ uint32_t smem_u32(const void* p) {
    uint32_t a;
    asm("{ .reg .u64 t; cvta.to.shared.u64 t, %1; cvt.u32.u64 %0, t; }"
        : "=r"(a) : "l"(p));
    return a;
}

__device__ __forceinline__ void ldsm4(uint32_t addr, uint32_t r[4]) {
    asm volatile("ldmatrix.sync.aligned.m8n8.x4.shared.b16 {%0,%1,%2,%3}, [%4];"
                 : "=r"(r[0]), "=r"(r[1]), "=r"(r[2]), "=r"(r[3]) : "r"(addr));
}

__device__ __forceinline__ void mma_bf16(float d[4], const uint32_t a[4],
                                         uint32_t b0, uint32_t b1) {
    asm volatile(
        "mma.sync.aligned.m16n8k16.row.col.f32.bf16.bf16.f32 "
        "{%0,%1,%2,%3},{%4,%5,%6,%7},{%8,%9},{%0,%1,%2,%3};"
        : "+f"(d[0]), "+f"(d[1]), "+f"(d[2]), "+f"(d[3])
        : "r"(a[0]), "r"(a[1]), "r"(a[2]), "r"(a[3]), "r"(b0), "r"(b1));
}

__device__ __forceinline__ void cp16(uint32_t d, const void* s) {
    asm volatile("cp.async.cg.shared.global [%0], [%1], 16;"
                 :: "r"(d), "l"(s) : "memory");
}

// Accurate tanh independent of fast-math lowering.
__device__ __forceinline__ float tanh_acc(float v) {
    float ax = fabsf(v);
    if (ax < 0.25f) {
        float s = v * v;
        float p = fmaf(s, 0.021869488f, -0.05396825397f);
        p = fmaf(s, p, 0.13333333333f);
        p = fmaf(s, p, -0.33333333333f);
        return fmaf(v * s, p, v);
    } else {
        float e = expf(-2.0f * ax);
        float r = (1.0f - e) / (1.0f + e);
        return copysignf(r, v);
    }
}

// Stage one 64x128 bf16 chunk (hi and lo) into a padded A buffer.
__device__ __forceinline__ void copy_chunk(uint32_t abuf,
                                           const __nv_bfloat16* __restrict__ hh,
                                           const __nv_bfloat16* __restrict__ hl,
                                           int chunk) {
    const int tid = threadIdx.x;
    const __nv_bfloat16* sh = hh + chunk * KC;
    const __nv_bfloat16* sl = hl + chunk * KC;
#pragma unroll
    for (int i = 0; i < 4; ++i) {
        int seg = tid + i * NTH;            // 0..1023: 16B segments
        int row = seg >> 4;                 // 16 segs per 256B row
        int c16 = seg & 15;
        uint32_t doff = (uint32_t)row * A_PITCH + (uint32_t)c16 * 16u;
        const char* gs = (const char*)(sh + (size_t)row * RH) + c16 * 16;
        cp16(abuf + doff, gs);
        const char* gl = (const char*)(sl + (size_t)row * RH) + c16 * 16;
        cp16(abuf + A_SPLIT + doff, gl);
    }
}

__global__ void __launch_bounds__(NTH, 1)
rnn_init_kernel() {
    int idx = blockIdx.x * blockDim.x + threadIdx.x;
    if (idx < RB * RH) {
        g_hh[0][idx] = __float2bfloat16(0.0f);
        g_hl[0][idx] = __float2bfloat16(0.0f);
    }
    if (idx < NM) g_bar[idx] = 0u;
}

__global__ void __launch_bounds__(NTH, 1)
rnn_mma_kernel(const float* __restrict__ x,
               const float* __restrict__ whx,
               const float* __restrict__ whh,
               const float* __restrict__ bias_h) {
    extern __shared__ char smem[];
    const uint32_t sb = smem_u32(smem);
    const uint32_t swh = sb + SW_HI;
    const uint32_t swl = sb + SW_LO;
    const uint32_t sa = sb + SA_OFF;

    const int tid = threadIdx.x;
    const int wid = tid >> 5;
    const int lane = tid & 31;
    const int bid = blockIdx.x;
    const int m = bid >> 5;              // 0..3 batch group
    const int n = bid & 31;              // 0..31 j tile
    const int jg0 = n * NT;
    const int brow0 = m * MT;

    const int wm = wid & 3;              // warp m16 tile 0..3
    const int wn = wid >> 2;             // warp n16 tile 0..1

    // whh slice -> resident SMEM, split hi/lo bf16, padded rows.
    for (int idx = tid; idx < NT * (RH / 2); idx += NTH) {
        int jl = idx >> 9;                  // /512
        int k2 = (idx & 511) * 2;
        float2 wv = *reinterpret_cast<const float2*>(
            &whh[(size_t)(jg0 + jl) * RH + k2]);
        __nv_bfloat16 h0 = __float2bfloat16(wv.x);
        __nv_bfloat16 l0 = __float2bfloat16(wv.x - __bfloat162float(h0));
        __nv_bfloat16 h1 = __float2bfloat16(wv.y);
        __nv_bfloat16 l1 = __float2bfloat16(wv.y - __bfloat162float(h1));
        uint32_t off = (uint32_t)jl * W_PITCH + (uint32_t)k2 * 2u;
        __nv_bfloat162 p2h; p2h.x = h0; p2h.y = h1;
        __nv_bfloat162 p2l; p2l.x = l0; p2l.y = l1;
        *reinterpret_cast<__nv_bfloat162*>(smem + SW_HI + off) = p2h;
        *reinterpret_cast<__nv_bfloat162*>(smem + SW_LO + off) = p2l;
    }

    // ldmatrix source addresses
    const uint32_t a_off = (uint32_t)(wm * 16 + (lane & 15)) * A_PITCH +
                           (uint32_t)(lane >> 4) * 16u;
    const int brn = wn * 16 + (lane & 7) + ((lane & 16) ? 8 : 0);
    const uint32_t b_off = (uint32_t)brn * W_PITCH +
                           (uint32_t)((lane >> 3) & 1) * 16u;

    // Epilogue constants
    const int r0 = wm * 16 + (lane >> 2);         // local m row (and +8)
    const int cc = wn * 16 + 2 * (lane & 3);      // local n col (even pair)
    float wx[4], bs[4];
    wx[0] = whx[jg0 + cc];      bs[0] = bias_h[jg0 + cc];
    wx[1] = whx[jg0 + cc + 1];  bs[1] = bias_h[jg0 + cc + 1];
    wx[2] = whx[jg0 + cc + 8];  bs[2] = bias_h[jg0 + cc + 8];
    wx[3] = whx[jg0 + cc + 9];  bs[3] = bias_h[jg0 + cc + 9];
    const int bg0 = brow0 + r0;          // global rows bg0 and bg0+8

    __syncthreads();
    volatile unsigned int* barp = &g_bar[m];

    for (int t = 0; t < RT; ++t) {
        const __nv_bfloat16* hh = &g_hh[t & 1][(size_t)brow0 * RH];
        const __nv_bfloat16* hl = &g_hl[t & 1][(size_t)brow0 * RH];

        copy_chunk(sa, hh, hl, 0);
        asm volatile("cp.async.commit_group;" ::: "memory");
        copy_chunk(sa + A_BUF, hh, hl, 1);
        asm volatile("cp.async.commit_group;" ::: "memory");

        float xb0 = x[(size_t)bg0 * RT + t];
        float xb1 = x[(size_t)(bg0 + 8) * RT + t];

        float dhh[8], dhl[8], dlh[8];
#pragma unroll
        for (int i = 0; i < 8; ++i) { dhh[i] = 0.f; dhl[i] = 0.f; dlh[i] = 0.f; }

#pragma unroll 1
        for (int c = 0; c < NCH; ++c) {
            if (c < NCH - 1) asm volatile("cp.async.wait_group 1;" ::: "memory");
            else             asm volatile("cp.async.wait_group 0;" ::: "memory");
            __syncthreads();

            const uint32_t ab = sa + (uint32_t)(c & 1) * A_BUF;
#pragma unroll
            for (int ks = 0; ks < 8; ++ks) {
                uint32_t ahi[4], alo[4], bhi[4], blo[4];
                ldsm4(ab + a_off + (uint32_t)ks * 32u, ahi);
                ldsm4(ab + A_SPLIT + a_off + (uint32_t)ks * 32u, alo);
                uint32_t kb = (uint32_t)(c * KC + ks * 16) * 2u;
                ldsm4(swh + b_off + kb, bhi);
                ldsm4(swl + b_off + kb, blo);
                mma_bf16(dhh + 0, ahi, bhi[0], bhi[1]);
                mma_bf16(dhh + 4, ahi, bhi[2], bhi[3]);
                mma_bf16(dhl + 0, ahi, blo[0], blo[1]);
                mma_bf16(dhl + 4, ahi, blo[2], blo[3]);
                mma_bf16(dlh + 0, alo, bhi[0], bhi[1]);
                mma_bf16(dlh + 4, alo, bhi[2], bhi[3]);
            }
            __syncthreads();
            if (c + 2 < NCH) {
                copy_chunk(sa + (uint32_t)(c & 1) * A_BUF, hh, hl, c + 2);
                asm volatile("cp.async.commit_group;" ::: "memory");
            }
        }

        // Epilogue: sum products, add input + bias, tanh, split hi/lo, store.
        const int ob = (t + 1) & 1;
        float v[8];
#pragma unroll
        for (int i = 0; i < 8; ++i) v[i] = dhh[i] + dhl[i] + dlh[i];
        // index map: (0,1)=r0,cc/cc+1; (2,3)=r0+8; (4,5)=r0,cc+8/9; (6,7)=r0+8
        float hv[8];
        hv[0] = tanh_acc(v[0] + fmaf(xb0, wx[0], bs[0]));
        hv[1] = tanh_acc(v[1] + fmaf(xb0, wx[1], bs[1]));
        hv[2] = tanh_acc(v[2] + fmaf(xb1, wx[0], bs[0]));
        hv[3] = tanh_acc(v[3] + fmaf(xb1, wx[1], bs[1]));
        hv[4] = tanh_acc(v[4] + fmaf(xb0, wx[2], bs[2]));
        hv[5] = tanh_acc(v[5] + fmaf(xb0, wx[3], bs[3]));
        hv[6] = tanh_acc(v[6] + fmaf(xb1, wx[2], bs[2]));
        hv[7] = tanh_acc(v[7] + fmaf(xb1, wx[3], bs[3]));

#pragma unroll
        for (int g = 0; g < 4; ++g) {
            // pairs: g0:(row bg0, col cc), g1:(bg0+8, cc), g2:(bg0, cc+8), g3:(bg0+8, cc+8)
            int rr = bg0 + ((g & 1) ? 8 : 0);
            int jc = jg0 + cc + ((g & 2) ? 8 : 0);
            float a = hv[(g & 2) * 2 + (g & 1) * 2 + 0];
            float b = hv[(g & 2) * 2 + (g & 1) * 2 + 1];
            __nv_bfloat16 ah = __float2bfloat16(a);
            __nv_bfloat16 bh = __float2bfloat16(b);
            __nv_bfloat16 al = __float2bfloat16(a - __bfloat162float(ah));
            __nv_bfloat16 bl = __float2bfloat16(b - __bfloat162float(bh));
            __nv_bfloat162 ph; ph.x = ah; ph.y = bh;
            __nv_bfloat162 pl; pl.x = al; pl.y = bl;
            size_t po = (size_t)rr * RH + jc;
            *reinterpret_cast<__nv_bfloat162*>(&g_hh[ob][po]) = ph;
            *reinterpret_cast<__nv_bfloat162*>(&g_hl[ob][po]) = pl;
        }

        // Per-group barrier (32 CTAs), monotonic counter reset by init kernel.
        __threadfence();
        __syncthreads();
        if (tid == 0) {
            atomicAdd(&g_bar[m], 1u);
            unsigned int target = (unsigned int)(t + 1) * NN;
            while (*barp < target) { }
            __threadfence();
        }
        __syncthreads();
    }
}

// p[b][c] = (h_hi + h_lo)[b] . wph[c] + bias_p[c]; final h is in buffer 0.
__global__ void __launch_bounds__(RB, 1)
rnn_proj_kernel(const float* __restrict__ wph,
                const float* __restrict__ bias_p,
                float* __restrict__ out) {
    const int c = blockIdx.x;    // 0..9
    const int b = threadIdx.x;   // 0..255
    const __nv_bfloat16* hh = &g_hh[0][(size_t)b * RH];
    const __nv_bfloat16* hl = &g_hl[0][(size_t)b * RH];
    const float* w = wph + (size_t)c * RH;
    float a0 = 0.0f, a1 = 0.0f;
#pragma unroll 4
    for (int k = 0; k < RH; k += 2) {
        __nv_bfloat162 h2 = *reinterpret_cast<const __nv_bfloat162*>(hh + k);
        __nv_bfloat162 l2 = *reinterpret_cast<const __nv_bfloat162*>(hl + k);
        a0 = fmaf(__bfloat162float(h2.x) + __bfloat162float(l2.x), w[k], a0);
        a1 = fmaf(__bfloat162float(h2.y) + __bfloat162float(l2.y), w[k + 1], a1);
    }
    out[b * RC + c] = a0 + a1 + bias_p[c];
}

extern "C" void kernel_launch(void* const* d_in, const int* in_sizes, int n_in,
                              void* d_out, int out_size) {
    (void)in_sizes; (void)n_in; (void)out_size;
    const float* x      = (const float*)d_in[0];   // [B, T]
    const float* whx    = (const float*)d_in[1];   // [H, 1]
    const float* whh    = (const float*)d_in[2];   // [H, H]
    const float* bias_h = (const float*)d_in[3];   // [H]
    const float* wph    = (const float*)d_in[4];   // [C, H]
    const float* bias_p = (const float*)d_in[5];   // [C]
    float* out = (float*)d_out;                    // [B, C]

    cudaFuncSetAttribute(rnn_mma_kernel,
                         cudaFuncAttributeMaxDynamicSharedMemorySize, SMEM_BYTES);

    rnn_init_kernel<<<(RB * RH + NTH - 1) / NTH, NTH>>>();
    rnn_mma_kernel<<<NM * NN, NTH, SMEM_BYTES>>>(x, whx, whh, bias_h);
    rnn_proj_kernel<<<RC, RB>>>(wph, bias_p, out);
}